// round 11
// baseline (speedup 1.0000x reference)
#include <cuda_runtime.h>
#include <cstdint>

#define BB 4
#define HH 8
#define SEQ 2048
#define DM 512
#define DH 64
#define BHN (BB*HH)
#define QT 128
#define KT 64
#define NIT (SEQ/KT)

// ---------------- scratch ---------------------------------------------------
__device__ float g_Q[BHN*SEQ*DH];      // [bh][s][d]
__device__ float g_K[BHN*SEQ*DH];
__device__ float g_V[BHN*SEQ*DH];
__device__ float g_ctx[BB*SEQ*DM];
__device__ float g_tmp[BB*SEQ*DM];
__device__ float g_invl[BHN*SEQ];
__device__ unsigned g_mbits[(size_t)BB*SEQ*(SEQ/32)];   // packed mask bits

// ---------------- helpers ----------------------------------------------------
__device__ __forceinline__ float tf32r(float x) {
    float y; asm("cvt.rna.tf32.f32 %0, %1;" : "=f"(y) : "f"(x)); return y;
}
__device__ __forceinline__ void mma16n8k8(float* d, const uint32_t* a, uint32_t b0, uint32_t b1) {
    asm volatile("mma.sync.aligned.m16n8k8.row.col.f32.tf32.tf32.f32 "
                 "{%0,%1,%2,%3}, {%4,%5,%6,%7}, {%8,%9}, {%0,%1,%2,%3};"
                 : "+f"(d[0]), "+f"(d[1]), "+f"(d[2]), "+f"(d[3])
                 : "r"(a[0]), "r"(a[1]), "r"(a[2]), "r"(a[3]), "r"(b0), "r"(b1));
}
__device__ __forceinline__ void cpa16(void* s, const void* g) {
    uint32_t sa = (uint32_t)__cvta_generic_to_shared(s);
    asm volatile("cp.async.cg.shared.global [%0], [%1], 16;" :: "r"(sa), "l"(g) : "memory");
}
#define CPA_COMMIT() asm volatile("cp.async.commit_group;" ::: "memory")
#define CPA_WAIT(n)  asm volatile("cp.async.wait_group %0;" :: "n"(n) : "memory")

// ---------------- mask bit-pack ---------------------------------------------
__global__ __launch_bounds__(256) void pack_mask_kernel(const int* __restrict__ mask) {
    int gw = (blockIdx.x * 256 + threadIdx.x) >> 5;
    int lane = threadIdx.x & 31;
    size_t base = (size_t)gw * 1024;
    unsigned word = 0;
#pragma unroll
    for (int j = 0; j < 32; j++) {
        int v = mask[base + (size_t)j * 32 + lane];
        unsigned bits = __ballot_sync(0xffffffffu, v != 0);
        if (lane == j) word = bits;
    }
    g_mbits[(size_t)gw * 32 + lane] = word;
}

// ---------------- GEMM via mma.sync tf32, BK=32, cp.async double buffer ------
// C[8192x512] = A[8192x512] * W[512x512].  BM=128 BN=128 BK=32, 256 thr, 8 warps.
// Dynamic smem: As[2][128][36] + Bs[2][32][136] = 71680 B.  16 k-steps, 16 syncs.
#define GA_STRIDE (128 * 36)
#define GB_STRIDE (32 * 136)
#define SMEM_GEMM ((2 * GA_STRIDE + 2 * GB_STRIDE) * 4)
__global__ __launch_bounds__(256, 2) void gemm_tc_kernel(const float* __restrict__ Ain,
                                                         const float* __restrict__ W,
                                                         int mode) {
    const float* A = (mode == 3) ? g_ctx : Ain;
    extern __shared__ float gsm[];
    float* Asb = gsm;                       // [2][128*36]
    float* Bsb = gsm + 2 * GA_STRIDE;       // [2][32*136]

    const int tid = threadIdx.x;
    const int wid = tid >> 5, lane = tid & 31;
    const int g = lane >> 2, t = lane & 3;
    const int wm = (wid & 3) * 32;
    const int wn = (wid >> 2) * 64;
    const int m0 = blockIdx.y * 128, n0 = blockIdx.x * 128;

    // staging coords: A 128x32 (2 thr/row, 16 floats each), B 32x128 (8 thr/row, 16 floats)
    const int arow = tid >> 1, ak = (tid & 1) << 4;
    const int brow = tid >> 3, bn = (tid & 7) << 4;
    const float* Ap = A + (size_t)(m0 + arow) * DM + ak;
    const float* Bp = W + (size_t)brow * DM + n0 + bn;

    float Cc[2][8][4];
#pragma unroll
    for (int i = 0; i < 2; i++)
#pragma unroll
        for (int nn = 0; nn < 8; nn++)
#pragma unroll
            for (int r = 0; r < 4; r++) Cc[i][nn][r] = 0.f;

    // prologue: stage k-step 0
#pragma unroll
    for (int u = 0; u < 4; u++) {
        cpa16(&Asb[arow * 36 + ak + u * 4], Ap + u * 4);
        cpa16(&Bsb[brow * 136 + bn + u * 4], Bp + u * 4);
    }
    CPA_COMMIT();

    for (int it = 0; it < DM / 32; it++) {
        const int cur = it & 1;
        if (it + 1 < DM / 32) {
            const int nxt = cur ^ 1;
            const int k0n = (it + 1) * 32;
#pragma unroll
            for (int u = 0; u < 4; u++) {
                cpa16(&Asb[nxt * GA_STRIDE + arow * 36 + ak + u * 4], Ap + k0n + u * 4);
                cpa16(&Bsb[nxt * GB_STRIDE + brow * 136 + bn + u * 4], Bp + (size_t)k0n * DM + u * 4);
            }
            CPA_COMMIT();
            CPA_WAIT(1);
        } else {
            CPA_WAIT(0);
        }
        __syncthreads();

        const uint32_t* AsC = (const uint32_t*)(Asb + cur * GA_STRIDE);
        const uint32_t* BsC = (const uint32_t*)(Bsb + cur * GB_STRIDE);
#pragma unroll
        for (int kk = 0; kk < 4; kk++) {
            const int kb = kk * 8;
            uint32_t a[2][4];
#pragma unroll
            for (int i = 0; i < 2; i++) {
                int rbase = (wm + i * 16 + g) * 36;
                a[i][0] = AsC[rbase + kb + t];
                a[i][1] = AsC[rbase + 288 + kb + t];      // +8 rows * 36
                a[i][2] = AsC[rbase + kb + t + 4];
                a[i][3] = AsC[rbase + 288 + kb + t + 4];
            }
#pragma unroll
            for (int nn = 0; nn < 8; nn++) {
                uint32_t b0 = BsC[(kb + t) * 136 + wn + nn * 8 + g];
                uint32_t b1 = BsC[(kb + t + 4) * 136 + wn + nn * 8 + g];
#pragma unroll
                for (int i = 0; i < 2; i++) mma16n8k8(Cc[i][nn], a[i], b0, b1);
            }
        }
        __syncthreads();
    }

    // epilogue: rows (wm+16i+g, +8), cols (wn+nn*8+2t, +1); h=(n0+coln)>>6
    const int hbase = n0 >> 6;
#pragma unroll
    for (int i = 0; i < 2; i++) {
#pragma unroll
        for (int rr = 0; rr < 2; rr++) {
            int m = m0 + wm + i * 16 + g + rr * 8;
            int bidx = m >> 11, s = m & 2047;
#pragma unroll
            for (int nn = 0; nn < 8; nn++) {
                int coln = wn + nn * 8 + 2 * t;
                float2 v = make_float2(Cc[i][nn][rr * 2 + 0], Cc[i][nn][rr * 2 + 1]);
                if (mode == 3) {
                    *(float2*)&g_tmp[(size_t)m * DM + n0 + coln] = v;
                } else {
                    int h = hbase + (coln >> 6);
                    int d = coln & 63;
                    float* dst = (mode == 0) ? g_Q : (mode == 1) ? g_K : g_V;
                    *(float2*)&dst[(((size_t)bidx * HH + h) * SEQ + s) * DH + d] = v;
                }
            }
        }
    }
}

// ---------------- tensor-core attention: fused per-n softmax+PV pipeline -----
// 256 threads (8 warps); block = 128 q rows of one (b,h); warp w owns rows w*16..+15.
// Per k-tile: QK mma -> for each n-group: mask/exp/STG/shfl/PV in one window.
#define TILE_F (64 * 68)                 // floats per K or V tile
#define BUF_F  (2 * TILE_F)              // floats per buffer (K+V)
__global__ __launch_bounds__(256, 2) void attn_mma_kernel(float* __restrict__ attn_out) {
    extern __shared__ float sm[];

    const int tid  = threadIdx.x;
    const int w    = tid >> 5;
    const int lane = tid & 31;
    const int gid  = lane >> 2;
    const int cL   = lane & 3;
    const int bh   = blockIdx.y;
    const int b    = bh >> 3, h = bh & 7;
    const int q0   = blockIdx.x * QT;
    const int lr   = w * 16 + gid;       // this thread: rows lr and lr+8

    const float* Qg = g_Q + (size_t)bh * SEQ * DH;
    const float* Kg = g_K + (size_t)bh * SEQ * DH;
    const float* Vg = g_V + (size_t)bh * SEQ * DH;

    // ---- stage Q tile [128][64] (RNA tf32), grab frags ----
#pragma unroll
    for (int j = 0; j < 8; j++) {
        int flat = j * 256 + tid;
        int row = flat >> 4, d4 = flat & 15;
        float4 v = *(const float4*)(Qg + (size_t)(q0 + row) * DH + d4 * 4);
        v.x = tf32r(v.x); v.y = tf32r(v.y); v.z = tf32r(v.z); v.w = tf32r(v.w);
        *(float4*)&sm[row * 68 + d4 * 4] = v;
    }
    __syncthreads();
    uint32_t qa[8][4];
    {
        const uint32_t* QsU = (const uint32_t*)sm;
#pragma unroll
        for (int kk = 0; kk < 8; kk++) {
            qa[kk][0] = QsU[lr * 68 + kk * 8 + cL];
            qa[kk][1] = QsU[(lr + 8) * 68 + kk * 8 + cL];
            qa[kk][2] = QsU[lr * 68 + kk * 8 + cL + 4];
            qa[kk][3] = QsU[(lr + 8) * 68 + kk * 8 + cL + 4];
        }
    }
    __syncthreads();   // all Q reads done before cp.async overwrites the region

    float Cacc[8][4];
#pragma unroll
    for (int dt = 0; dt < 8; dt++)
#pragma unroll
        for (int r = 0; r < 4; r++) Cacc[dt][r] = 0.f;
    float lsum0 = 0.f, lsum1 = 0.f;

    const size_t mrow0 = ((size_t)b * SEQ + q0 + lr) * (SEQ / 32);
    const size_t mrow1 = ((size_t)b * SEQ + q0 + lr + 8) * (SEQ / 32);
    float* aprow0 = attn_out + ((size_t)bh * SEQ + q0 + lr) * SEQ;
    float* aprow1 = aprow0 + 8 * SEQ;

    // per-thread staging: 4 threads/row, thread covers floats [16*(tid&3), +16)
    const int srow = tid >> 2;           // 0..63
    const int sd4  = (tid & 3) << 4;     // 0,16,32,48

    // prologue: stage tile 0 into buf0
    {
        const float* kp = Kg + (size_t)srow * DH + sd4;
        const float* vp = Vg + (size_t)srow * DH + sd4;
        float* kb = sm + srow * 68 + sd4;
        float* vb = sm + TILE_F + srow * 68 + sd4;
#pragma unroll
        for (int u = 0; u < 4; u++) {
            cpa16(kb + u * 4, kp + u * 4);
            cpa16(vb + u * 4, vp + u * 4);
        }
    }
    CPA_COMMIT();

    const int src  = (lane & ~3) | (cL >> 1);
    const int src2 = src + 2;

    for (int i = 0; i < NIT; i++) {
        const int k0 = i * KT;
        const int cur = i & 1;
        if (i + 1 < NIT) {
            const int nxt = cur ^ 1;
            const size_t off = (size_t)(i + 1) * KT * DH + (size_t)srow * DH + sd4;
            float* kb = sm + nxt * BUF_F + srow * 68 + sd4;
            float* vb = sm + nxt * BUF_F + TILE_F + srow * 68 + sd4;
#pragma unroll
            for (int u = 0; u < 4; u++) {
                cpa16(kb + u * 4, Kg + off + u * 4);
                cpa16(vb + u * 4, Vg + off + u * 4);
            }
            CPA_COMMIT();
            CPA_WAIT(1);
        } else {
            CPA_WAIT(0);
        }

        // hoist mask loads: latency hides under QK mma
        uint2 m2l = *(const uint2*)&g_mbits[mrow0 + (k0 >> 5)];
        uint2 m2h = *(const uint2*)&g_mbits[mrow1 + (k0 >> 5)];
        __syncthreads();

        const uint32_t* KsU = (const uint32_t*)(sm + cur * BUF_F);
        const uint32_t* VsU = KsU + TILE_F;

        // QK: S[16 q][64 k] per warp
        float S[8][4];
#pragma unroll
        for (int n = 0; n < 8; n++)
#pragma unroll
            for (int r = 0; r < 4; r++) S[n][r] = 0.f;
#pragma unroll
        for (int kk = 0; kk < 8; kk++) {
#pragma unroll
            for (int n = 0; n < 8; n++) {
                uint32_t b0 = KsU[(n * 8 + gid) * 68 + kk * 8 + cL];
                uint32_t b1 = KsU[(n * 8 + gid) * 68 + kk * 8 + cL + 4];
                mma16n8k8(S[n], qa[kk], b0, b1);
            }
        }

        unsigned ml[2] = {m2l.x, m2l.y};
        unsigned mh[2] = {m2h.x, m2h.y};

        // fused per-n window: mask+exp -> STG -> shfl -> PV mma
#pragma unroll
        for (int n = 0; n < 8; n++) {
            int shift = (n & 3) * 8 + 2 * cL;
            unsigned bl  = ml[n >> 2] >> shift;
            unsigned bhh = mh[n >> 2] >> shift;
            float e0 = (bl  & 1u) ? 0.f : __expf(S[n][0] * 0.125f);
            float e1 = (bl  & 2u) ? 0.f : __expf(S[n][1] * 0.125f);
            float e2 = (bhh & 1u) ? 0.f : __expf(S[n][2] * 0.125f);
            float e3 = (bhh & 2u) ? 0.f : __expf(S[n][3] * 0.125f);
            lsum0 += e0 + e1;
            lsum1 += e2 + e3;
            int col = k0 + n * 8 + 2 * cL;
            *(float2*)(aprow0 + col) = make_float2(e0, e1);
            *(float2*)(aprow1 + col) = make_float2(e2, e3);

            float t00 = __shfl_sync(0xffffffffu, e0, src);
            float t01 = __shfl_sync(0xffffffffu, e1, src);
            float t20 = __shfl_sync(0xffffffffu, e0, src2);
            float t21 = __shfl_sync(0xffffffffu, e1, src2);
            float u00 = __shfl_sync(0xffffffffu, e2, src);
            float u01 = __shfl_sync(0xffffffffu, e3, src);
            float u20 = __shfl_sync(0xffffffffu, e2, src2);
            float u21 = __shfl_sync(0xffffffffu, e3, src2);
            uint32_t pa[4];
            pa[0] = __float_as_uint((cL & 1) ? t01 : t00);
            pa[1] = __float_as_uint((cL & 1) ? u01 : u00);
            pa[2] = __float_as_uint((cL & 1) ? t21 : t20);
            pa[3] = __float_as_uint((cL & 1) ? u21 : u20);
#pragma unroll
            for (int dt = 0; dt < 8; dt++) {
                uint32_t b0 = VsU[(n * 8 + cL) * 68 + dt * 8 + gid];
                uint32_t b1 = VsU[(n * 8 + cL + 4) * 68 + dt * 8 + gid];
                mma16n8k8(Cacc[dt], pa, b0, b1);
            }
        }
        __syncthreads();
    }

    lsum0 += __shfl_xor_sync(0xffffffffu, lsum0, 1);
    lsum0 += __shfl_xor_sync(0xffffffffu, lsum0, 2);
    lsum1 += __shfl_xor_sync(0xffffffffu, lsum1, 1);
    lsum1 += __shfl_xor_sync(0xffffffffu, lsum1, 2);
    float inv0 = 1.0f / lsum0;
    float inv1 = 1.0f / lsum1;
    if (cL == 0) {
        g_invl[(size_t)bh * SEQ + q0 + lr]     = inv0;
        g_invl[(size_t)bh * SEQ + q0 + lr + 8] = inv1;
    }
    float* cp0 = g_ctx + ((size_t)b * SEQ + q0 + lr) * DM + h * DH;
    float* cp1 = cp0 + 8 * DM;
#pragma unroll
    for (int dt = 0; dt < 8; dt++) {
        int col = dt * 8 + 2 * cL;
        *(float2*)(cp0 + col) = make_float2(Cacc[dt][0] * inv0, Cacc[dt][1] * inv0);
        *(float2*)(cp1 + col) = make_float2(Cacc[dt][2] * inv1, Cacc[dt][3] * inv1);
    }
}

// ---------------- scale attn rows by 1/l ------------------------------------
__global__ void attn_norm_kernel(float* __restrict__ attn) {
    size_t i4 = (size_t)blockIdx.x * 256 + threadIdx.x;
    float inv = g_invl[i4 >> 9];
    float4* p = (float4*)attn + i4;
    float4 v = *p;
    v.x *= inv; v.y *= inv; v.z *= inv; v.w *= inv;
    *p = v;
}

// ---------------- layernorm(tmp + input_Q) ----------------------------------
__global__ __launch_bounds__(256) void ln_kernel(const float* __restrict__ inQ,
                                                 const float* __restrict__ gamma,
                                                 const float* __restrict__ beta,
                                                 float* __restrict__ out) {
    int row = blockIdx.x;
    int tid = threadIdx.x;
    const float* t  = g_tmp + (size_t)row * DM;
    const float* xq = inQ  + (size_t)row * DM;
    float2 a  = *(const float2*)(t  + tid * 2);
    float2 b2 = *(const float2*)(xq + tid * 2);
    float x0 = a.x + b2.x, x1 = a.y + b2.y;
    float s  = x0 + x1;
    float sq = x0 * x0 + x1 * x1;
#pragma unroll
    for (int o = 16; o; o >>= 1) {
        s  += __shfl_xor_sync(0xffffffffu, s,  o);
        sq += __shfl_xor_sync(0xffffffffu, sq, o);
    }
    __shared__ float ws[8], wq[8];
    int w = tid >> 5, lane = tid & 31;
    if (lane == 0) { ws[w] = s; wq[w] = sq; }
    __syncthreads();
    float ts = 0.f, tq = 0.f;
#pragma unroll
    for (int k = 0; k < 8; k++) { ts += ws[k]; tq += wq[k]; }
    float mu  = ts * (1.f / DM);
    float var = tq * (1.f / DM) - mu * mu;
    float r = rsqrtf(var + 1e-5f);
    float2 g  = *(const float2*)(gamma + tid * 2);
    float2 be = *(const float2*)(beta  + tid * 2);
    float2 o;
    o.x = (x0 - mu) * r * g.x + be.x;
    o.y = (x1 - mu) * r * g.y + be.y;
    *(float2*)(out + (size_t)row * DM + tid * 2) = o;
}

// ---------------- launch ----------------------------------------------------
extern "C" void kernel_launch(void* const* d_in, const int* in_sizes, int n_in,
                              void* d_out, int out_size) {
    const float* inQ  = (const float*)d_in[0];
    const float* inK  = (const float*)d_in[1];
    const float* inV  = (const float*)d_in[2];
    const int*   mask = (const int*)d_in[3];
    const float* WQ   = (const float*)d_in[4];
    const float* WK   = (const float*)d_in[5];
    const float* WV   = (const float*)d_in[6];
    const float* Wfc  = (const float*)d_in[7];
    const float* gamma = (const float*)d_in[8];
    const float* beta  = (const float*)d_in[9];

    float* out = (float*)d_out;
    const long OUT_ELEMS = (long)BB * SEQ * DM;
    float* attn_out = out + OUT_ELEMS;

    pack_mask_kernel<<<2048, 256>>>(mask);

    cudaFuncSetAttribute(gemm_tc_kernel, cudaFuncAttributeMaxDynamicSharedMemorySize, SMEM_GEMM);
    dim3 gb(4, 64);
    gemm_tc_kernel<<<gb, 256, SMEM_GEMM>>>(inQ, WQ, 0);
    gemm_tc_kernel<<<gb, 256, SMEM_GEMM>>>(inK, WK, 1);
    gemm_tc_kernel<<<gb, 256, SMEM_GEMM>>>(inV, WV, 2);

    const int SMEM_ATTN = 2 * BUF_F * 4;   // 69632 B
    cudaFuncSetAttribute(attn_mma_kernel, cudaFuncAttributeMaxDynamicSharedMemorySize, SMEM_ATTN);
    attn_mma_kernel<<<dim3(SEQ / QT, BHN), 256, SMEM_ATTN>>>(attn_out);

    attn_norm_kernel<<<131072, 256>>>(attn_out);

    gemm_tc_kernel<<<gb, 256, SMEM_GEMM>>>(inQ /*ignored*/, Wfc, 3);
    ln_kernel<<<BB * SEQ, 256>>>(inQ, gamma, beta, out);
}

// round 12
// speedup vs baseline: 1.5307x; 1.5307x over previous
#include <cuda_runtime.h>
#include <cuda_fp16.h>
#include <cstdint>

#define BB 4
#define HH 8
#define SEQ 2048
#define DM 512
#define DH 64
#define BHN (BB*HH)
#define QT 128
#define KT 64
#define NIT (SEQ/KT)

// ---------------- scratch ---------------------------------------------------
__device__ __half g_Qh[(size_t)BHN*SEQ*DH];   // [bh][s][d]
__device__ __half g_Kh[(size_t)BHN*SEQ*DH];   // [bh][s][d]
__device__ __half g_Vt[(size_t)BHN*DH*SEQ];   // [bh][d][s]  (transposed)
__device__ float g_ctx[BB*SEQ*DM];
__device__ float g_tmp[BB*SEQ*DM];
__device__ float g_invl[BHN*SEQ];
__device__ unsigned g_mbits[(size_t)BB*SEQ*(SEQ/32)];   // packed mask bits

// ---------------- helpers ----------------------------------------------------
__device__ __forceinline__ float tf32r(float x) {
    float y; asm("cvt.rna.tf32.f32 %0, %1;" : "=f"(y) : "f"(x)); return y;
}
__device__ __forceinline__ void mma16n8k8(float* d, const uint32_t* a, uint32_t b0, uint32_t b1) {
    asm volatile("mma.sync.aligned.m16n8k8.row.col.f32.tf32.tf32.f32 "
                 "{%0,%1,%2,%3}, {%4,%5,%6,%7}, {%8,%9}, {%0,%1,%2,%3};"
                 : "+f"(d[0]), "+f"(d[1]), "+f"(d[2]), "+f"(d[3])
                 : "r"(a[0]), "r"(a[1]), "r"(a[2]), "r"(a[3]), "r"(b0), "r"(b1));
}
__device__ __forceinline__ void mma16n8k16f16(float* d, const uint32_t* a, uint32_t b0, uint32_t b1) {
    asm volatile("mma.sync.aligned.m16n8k16.row.col.f32.f16.f16.f32 "
                 "{%0,%1,%2,%3}, {%4,%5,%6,%7}, {%8,%9}, {%0,%1,%2,%3};"
                 : "+f"(d[0]), "+f"(d[1]), "+f"(d[2]), "+f"(d[3])
                 : "r"(a[0]), "r"(a[1]), "r"(a[2]), "r"(a[3]), "r"(b0), "r"(b1));
}
__device__ __forceinline__ void cpa16(void* s, const void* g) {
    uint32_t sa = (uint32_t)__cvta_generic_to_shared(s);
    asm volatile("cp.async.cg.shared.global [%0], [%1], 16;" :: "r"(sa), "l"(g) : "memory");
}
#define CPA_COMMIT() asm volatile("cp.async.commit_group;" ::: "memory")
#define CPA_WAIT(n)  asm volatile("cp.async.wait_group %0;" :: "n"(n) : "memory")
__device__ __forceinline__ uint32_t packh2(float lo, float hi) {
    __half2 t = __floats2half2_rn(lo, hi);
    return *reinterpret_cast<uint32_t*>(&t);
}

// ---------------- mask bit-pack ---------------------------------------------
__global__ __launch_bounds__(256) void pack_mask_kernel(const int* __restrict__ mask) {
    int gw = (blockIdx.x * 256 + threadIdx.x) >> 5;
    int lane = threadIdx.x & 31;
    size_t base = (size_t)gw * 1024;
    unsigned word = 0;
#pragma unroll
    for (int j = 0; j < 32; j++) {
        int v = mask[base + (size_t)j * 32 + lane];
        unsigned bits = __ballot_sync(0xffffffffu, v != 0);
        if (lane == j) word = bits;
    }
    g_mbits[(size_t)gw * 32 + lane] = word;
}

// ---------------- GEMM via mma.sync tf32, BK=16, cp.async (R10 proven) -------
// mode 0 -> g_Qh (half), 1 -> g_Kh (half), 2 -> g_Vt (half transposed), 3 -> g_tmp (fp32)
__global__ __launch_bounds__(256, 2) void gemm_tc_kernel(const float* __restrict__ Ain,
                                                         const float* __restrict__ W,
                                                         int mode) {
    const float* A = (mode == 3) ? g_ctx : Ain;
    __shared__ float As[2][128][20];
    __shared__ float Bs[2][16][136];

    const int tid = threadIdx.x;
    const int wid = tid >> 5, lane = tid & 31;
    const int g = lane >> 2, t = lane & 3;
    const int wm = (wid & 3) * 32;
    const int wn = (wid >> 2) * 64;
    const int m0 = blockIdx.y * 128, n0 = blockIdx.x * 128;

    const int arow = tid >> 2, ak = (tid & 3) << 2;
    const int brow = tid >> 5, bn = (tid & 31) << 2;
    const float* Ap0 = A + (size_t)(m0 + arow) * DM + ak;
    const float* Ap1 = Ap0 + (size_t)64 * DM;
    const float* Bp0 = W + (size_t)brow * DM + n0 + bn;
    const float* Bp1 = Bp0 + (size_t)8 * DM;

    float Cc[2][8][4];
#pragma unroll
    for (int i = 0; i < 2; i++)
#pragma unroll
        for (int nn = 0; nn < 8; nn++)
#pragma unroll
            for (int r = 0; r < 4; r++) Cc[i][nn][r] = 0.f;

    cpa16(&As[0][arow][ak],      Ap0);
    cpa16(&As[0][arow + 64][ak], Ap1);
    cpa16(&Bs[0][brow][bn],      Bp0);
    cpa16(&Bs[0][brow + 8][bn],  Bp1);
    CPA_COMMIT();

    for (int it = 0; it < DM / 16; it++) {
        const int cur = it & 1;
        if (it + 1 < DM / 16) {
            const int nxt = cur ^ 1;
            const int k0n = (it + 1) * 16;
            cpa16(&As[nxt][arow][ak],      Ap0 + k0n);
            cpa16(&As[nxt][arow + 64][ak], Ap1 + k0n);
            cpa16(&Bs[nxt][brow][bn],      Bp0 + (size_t)k0n * DM);
            cpa16(&Bs[nxt][brow + 8][bn],  Bp1 + (size_t)k0n * DM);
            CPA_COMMIT();
            CPA_WAIT(1);
        } else {
            CPA_WAIT(0);
        }
        __syncthreads();

        const uint32_t* AsC = (const uint32_t*)As[cur];
        const uint32_t* BsC = (const uint32_t*)Bs[cur];
#pragma unroll
        for (int kk = 0; kk < 2; kk++) {
            const int kb = kk * 8;
            uint32_t a[2][4];
#pragma unroll
            for (int i = 0; i < 2; i++) {
                int rbase = (wm + i * 16 + g) * 20;
                a[i][0] = AsC[rbase + kb + t];
                a[i][1] = AsC[rbase + 160 + kb + t];
                a[i][2] = AsC[rbase + kb + t + 4];
                a[i][3] = AsC[rbase + 160 + kb + t + 4];
            }
#pragma unroll
            for (int nn = 0; nn < 8; nn++) {
                uint32_t b0 = BsC[(kb + t) * 136 + wn + nn * 8 + g];
                uint32_t b1 = BsC[(kb + t + 4) * 136 + wn + nn * 8 + g];
#pragma unroll
                for (int i = 0; i < 2; i++) mma16n8k8(Cc[i][nn], a[i], b0, b1);
            }
        }
        __syncthreads();
    }

    // epilogue: rows (wm+16i+g, +8), cols (wn+nn*8+2t, +1); h=(n0+coln)>>6
    const int hbase = n0 >> 6;
#pragma unroll
    for (int i = 0; i < 2; i++) {
#pragma unroll
        for (int rr = 0; rr < 2; rr++) {
            int m = m0 + wm + i * 16 + g + rr * 8;
            int bidx = m >> 11, s = m & 2047;
#pragma unroll
            for (int nn = 0; nn < 8; nn++) {
                int coln = wn + nn * 8 + 2 * t;
                float2 v = make_float2(Cc[i][nn][rr * 2 + 0], Cc[i][nn][rr * 2 + 1]);
                if (mode == 3) {
                    *(float2*)&g_tmp[(size_t)m * DM + n0 + coln] = v;
                } else {
                    int hh = hbase + (coln >> 6);
                    int d = coln & 63;
                    int bh = bidx * HH + hh;
                    if (mode == 2) {
                        g_Vt[((size_t)bh * DH + d)     * SEQ + s] = __float2half_rn(v.x);
                        g_Vt[((size_t)bh * DH + d + 1) * SEQ + s] = __float2half_rn(v.y);
                    } else {
                        __half2 hv = __floats2half2_rn(v.x, v.y);
                        __half* dst = (mode == 0) ? g_Qh : g_Kh;
                        *(__half2*)&dst[((size_t)bh * SEQ + s) * DH + d] = hv;
                    }
                }
            }
        }
    }
}

// ---------------- fp16 tensor-core attention ---------------------------------
// 256 threads (8 warps); block = 128 q rows of one (b,h); warp w owns rows w*16..+15.
// fp16 m16n8k16: QK C-frag pairs == PV A-frag pairs -> NO shuffles.
// SMEM (halves): Qs[128][72] | Kbuf[2][64][72] | Vbuf[2][64][72] = 55296 B
#define QS_OFF 0
#define K_OFF  (128 * 72)
#define V_OFF  (K_OFF + 2 * 64 * 72)
#define TILE_H (64 * 72)
#define SMEM_ATTN ((128 * 72 + 4 * 64 * 72) * 2)
__global__ __launch_bounds__(256, 2) void attn_mma_kernel(float* __restrict__ attn_out) {
    extern __shared__ __half smh[];

    const int tid  = threadIdx.x;
    const int w    = tid >> 5;
    const int lane = tid & 31;
    const int gid  = lane >> 2;
    const int cL   = lane & 3;
    const int bh   = blockIdx.y;
    const int b    = bh >> 3, h = bh & 7;
    const int q0   = blockIdx.x * QT;
    const int lr   = w * 16 + gid;       // this thread: rows lr and lr+8

    const __half* Qg = g_Qh + (size_t)bh * SEQ * DH;
    const __half* Kg = g_Kh + (size_t)bh * SEQ * DH;
    const __half* Vg = g_Vt + (size_t)bh * DH * SEQ;

    // ---- stage Q tile [128][64h] via cp.async (rows stride 72 halves) ----
#pragma unroll
    for (int j = 0; j < 4; j++) {
        int flat = j * 256 + tid;
        int row = flat >> 3, seg = flat & 7;            // seg: 8 halves = 16B
        cpa16(&smh[QS_OFF + row * 72 + seg * 8], Qg + (size_t)(q0 + row) * DH + seg * 8);
    }
    CPA_COMMIT();
    CPA_WAIT(0);
    __syncthreads();

    // Q A-frags (half2 words): a0=(lr,2cL..), a1=(lr+8,..), a2=(lr,8+2cL..), a3=(lr+8,..)
    uint32_t qa[4][4];
    {
        const uint32_t* Q2 = (const uint32_t*)smh;
#pragma unroll
        for (int kk = 0; kk < 4; kk++) {
            qa[kk][0] = Q2[lr * 36 + kk * 8 + cL];
            qa[kk][1] = Q2[(lr + 8) * 36 + kk * 8 + cL];
            qa[kk][2] = Q2[lr * 36 + kk * 8 + cL + 4];
            qa[kk][3] = Q2[(lr + 8) * 36 + kk * 8 + cL + 4];
        }
    }

    float Cacc[8][4];
#pragma unroll
    for (int dt = 0; dt < 8; dt++)
#pragma unroll
        for (int r = 0; r < 4; r++) Cacc[dt][r] = 0.f;
    float lsum0 = 0.f, lsum1 = 0.f;

    const size_t mrow0 = ((size_t)b * SEQ + q0 + lr) * (SEQ / 32);
    const size_t mrow1 = ((size_t)b * SEQ + q0 + lr + 8) * (SEQ / 32);
    float* aprow0 = attn_out + ((size_t)bh * SEQ + q0 + lr) * SEQ;
    float* aprow1 = aprow0 + 8 * SEQ;

    // K/V staging: 4 thr/row... row = tid>>2 (0..63), two 16B segs each
    const int srow = tid >> 2;
    const int sseg = (tid & 3) * 2;

    // prologue: stage tile 0 into buf0
#pragma unroll
    for (int u = 0; u < 2; u++) {
        int sg = sseg + u;
        cpa16(&smh[K_OFF + srow * 72 + sg * 8], Kg + (size_t)srow * DH + sg * 8);
        cpa16(&smh[V_OFF + srow * 72 + sg * 8], Vg + (size_t)srow * SEQ + sg * 8);
    }
    CPA_COMMIT();

    for (int i = 0; i < NIT; i++) {
        const int k0 = i * KT;
        const int cur = i & 1;
        if (i + 1 < NIT) {
            const int nxt = cur ^ 1;
            const int kn = k0 + KT;
#pragma unroll
            for (int u = 0; u < 2; u++) {
                int sg = sseg + u;
                cpa16(&smh[K_OFF + nxt * TILE_H + srow * 72 + sg * 8],
                      Kg + (size_t)(kn + srow) * DH + sg * 8);
                cpa16(&smh[V_OFF + nxt * TILE_H + srow * 72 + sg * 8],
                      Vg + (size_t)srow * SEQ + kn + sg * 8);
            }
            CPA_COMMIT();
            CPA_WAIT(1);
        } else {
            CPA_WAIT(0);
        }

        // hoist mask loads under the wait/sync
        uint2 m2l = *(const uint2*)&g_mbits[mrow0 + (k0 >> 5)];
        uint2 m2h = *(const uint2*)&g_mbits[mrow1 + (k0 >> 5)];
        __syncthreads();

        const uint32_t* Kw = (const uint32_t*)(smh + K_OFF + cur * TILE_H);
        const uint32_t* Vw = (const uint32_t*)(smh + V_OFF + cur * TILE_H);

        // QK: S[16 q][64 k] per warp, fp16 k16 steps
        float S[8][4];
#pragma unroll
        for (int n = 0; n < 8; n++)
#pragma unroll
            for (int r = 0; r < 4; r++) S[n][r] = 0.f;
#pragma unroll
        for (int kk = 0; kk < 4; kk++) {
#pragma unroll
            for (int n = 0; n < 8; n++) {
                uint32_t b0 = Kw[(n * 8 + gid) * 36 + kk * 8 + cL];
                uint32_t b1 = Kw[(n * 8 + gid) * 36 + kk * 8 + cL + 4];
                mma16n8k16f16(S[n], qa[kk], b0, b1);
            }
        }

        // mask + exp + attn STG + row-sum + pack fp16 pairs (no shuffles!)
        unsigned ml[2] = {m2l.x, m2l.y};
        unsigned mh[2] = {m2h.x, m2h.y};
        uint32_t h01[8], h23[8];
#pragma unroll
        for (int n = 0; n < 8; n++) {
            int shift = (n & 3) * 8 + 2 * cL;
            unsigned bl  = ml[n >> 2] >> shift;
            unsigned bhh = mh[n >> 2] >> shift;
            float e0 = (bl  & 1u) ? 0.f : __expf(S[n][0] * 0.125f);
            float e1 = (bl  & 2u) ? 0.f : __expf(S[n][1] * 0.125f);
            float e2 = (bhh & 1u) ? 0.f : __expf(S[n][2] * 0.125f);
            float e3 = (bhh & 2u) ? 0.f : __expf(S[n][3] * 0.125f);
            lsum0 += e0 + e1;
            lsum1 += e2 + e3;
            int col = k0 + n * 8 + 2 * cL;
            *(float2*)(aprow0 + col) = make_float2(e0, e1);
            *(float2*)(aprow1 + col) = make_float2(e2, e3);
            h01[n] = packh2(e0, e1);
            h23[n] = packh2(e2, e3);
        }

        // PV: ctx += P.V ; A-frags are this thread's own packed pairs
#pragma unroll
        for (int s = 0; s < 4; s++) {
            uint32_t pa[4] = {h01[2 * s], h23[2 * s], h01[2 * s + 1], h23[2 * s + 1]};
#pragma unroll
            for (int dt = 0; dt < 8; dt++) {
                uint32_t b0 = Vw[(dt * 8 + gid) * 36 + s * 8 + cL];
                uint32_t b1 = Vw[(dt * 8 + gid) * 36 + s * 8 + cL + 4];
                mma16n8k16f16(Cacc[dt], pa, b0, b1);
            }
        }
        __syncthreads();
    }

    lsum0 += __shfl_xor_sync(0xffffffffu, lsum0, 1);
    lsum0 += __shfl_xor_sync(0xffffffffu, lsum0, 2);
    lsum1 += __shfl_xor_sync(0xffffffffu, lsum1, 1);
    lsum1 += __shfl_xor_sync(0xffffffffu, lsum1, 2);
    float inv0 = 1.0f / lsum0;
    float inv1 = 1.0f / lsum1;
    if (cL == 0) {
        g_invl[(size_t)bh * SEQ + q0 + lr]     = inv0;
        g_invl[(size_t)bh * SEQ + q0 + lr + 8] = inv1;
    }
    float* cp0 = g_ctx + ((size_t)b * SEQ + q0 + lr) * DM + h * DH;
    float* cp1 = cp0 + 8 * DM;
#pragma unroll
    for (int dt = 0; dt < 8; dt++) {
        int col = dt * 8 + 2 * cL;
        *(float2*)(cp0 + col) = make_float2(Cacc[dt][0] * inv0, Cacc[dt][1] * inv0);
        *(float2*)(cp1 + col) = make_float2(Cacc[dt][2] * inv1, Cacc[dt][3] * inv1);
    }
}

// ---------------- scale attn rows by 1/l ------------------------------------
__global__ void attn_norm_kernel(float* __restrict__ attn) {
    size_t i4 = (size_t)blockIdx.x * 256 + threadIdx.x;
    float inv = g_invl[i4 >> 9];
    float4* p = (float4*)attn + i4;
    float4 v = *p;
    v.x *= inv; v.y *= inv; v.z *= inv; v.w *= inv;
    *p = v;
}

// ---------------- layernorm(tmp + input_Q) ----------------------------------
__global__ __launch_bounds__(256) void ln_kernel(const float* __restrict__ inQ,
                                                 const float* __restrict__ gamma,
                                                 const float* __restrict__ beta,
                                                 float* __restrict__ out) {
    int row = blockIdx.x;
    int tid = threadIdx.x;
    const float* t  = g_tmp + (size_t)row * DM;
    const float* xq = inQ  + (size_t)row * DM;
    float2 a  = *(const float2*)(t  + tid * 2);
    float2 b2 = *(const float2*)(xq + tid * 2);
    float x0 = a.x + b2.x, x1 = a.y + b2.y;
    float s  = x0 + x1;
    float sq = x0 * x0 + x1 * x1;
#pragma unroll
    for (int o = 16; o; o >>= 1) {
        s  += __shfl_xor_sync(0xffffffffu, s,  o);
        sq += __shfl_xor_sync(0xffffffffu, sq, o);
    }
    __shared__ float ws[8], wq[8];
    int w = tid >> 5, lane = tid & 31;
    if (lane == 0) { ws[w] = s; wq[w] = sq; }
    __syncthreads();
    float ts = 0.f, tq = 0.f;
#pragma unroll
    for (int k = 0; k < 8; k++) { ts += ws[k]; tq += wq[k]; }
    float mu  = ts * (1.f / DM);
    float var = tq * (1.f / DM) - mu * mu;
    float r = rsqrtf(var + 1e-5f);
    float2 g  = *(const float2*)(gamma + tid * 2);
    float2 be = *(const float2*)(beta  + tid * 2);
    float2 o;
    o.x = (x0 - mu) * r * g.x + be.x;
    o.y = (x1 - mu) * r * g.y + be.y;
    *(float2*)(out + (size_t)row * DM + tid * 2) = o;
}

// ---------------- launch ----------------------------------------------------
extern "C" void kernel_launch(void* const* d_in, const int* in_sizes, int n_in,
                              void* d_out, int out_size) {
    const float* inQ  = (const float*)d_in[0];
    const float* inK  = (const float*)d_in[1];
    const float* inV  = (const float*)d_in[2];
    const int*   mask = (const int*)d_in[3];
    const float* WQ   = (const float*)d_in[4];
    const float* WK   = (const float*)d_in[5];
    const float* WV   = (const float*)d_in[6];
    const float* Wfc  = (const float*)d_in[7];
    const float* gamma = (const float*)d_in[8];
    const float* beta  = (const float*)d_in[9];

    float* out = (float*)d_out;
    const long OUT_ELEMS = (long)BB * SEQ * DM;
    float* attn_out = out + OUT_ELEMS;

    pack_mask_kernel<<<2048, 256>>>(mask);

    dim3 gb(4, 64);
    gemm_tc_kernel<<<gb, 256>>>(inQ, WQ, 0);
    gemm_tc_kernel<<<gb, 256>>>(inK, WK, 1);
    gemm_tc_kernel<<<gb, 256>>>(inV, WV, 2);

    cudaFuncSetAttribute(attn_mma_kernel, cudaFuncAttributeMaxDynamicSharedMemorySize, SMEM_ATTN);
    attn_mma_kernel<<<dim3(SEQ / QT, BHN), 256, SMEM_ATTN>>>(attn_out);

    attn_norm_kernel<<<131072, 256>>>(attn_out);

    gemm_tc_kernel<<<gb, 256>>>(inQ /*ignored*/, Wfc, 3);
    ln_kernel<<<BB * SEQ, 256>>>(inQ, gamma, beta, out);
}

// round 13
// speedup vs baseline: 1.7657x; 1.1535x over previous
#include <cuda_runtime.h>
#include <cuda_fp16.h>
#include <cstdint>

#define BB 4
#define HH 8
#define SEQ 2048
#define DM 512
#define DH 64
#define BHN (BB*HH)
#define QT 128
#define KT 64
#define NIT (SEQ/KT)

// ---------------- scratch ---------------------------------------------------
__device__ __half g_inh[3][(size_t)BB*SEQ*DM];     // inputs Q/K/V in fp16
__device__ __half g_Wth[4][DM*DM];                 // W^T in fp16: [n][k]
__device__ __half g_Qh[(size_t)BHN*SEQ*DH];        // [bh][s][d]
__device__ __half g_Kh[(size_t)BHN*SEQ*DH];        // [bh][s][d]
__device__ __half g_Vt[(size_t)BHN*DH*SEQ];        // [bh][d][s]
__device__ __half g_ctxh[(size_t)BB*SEQ*DM];       // fp16 ctx
__device__ float g_tmp[BB*SEQ*DM];                 // fc output (fp32) for LN
__device__ unsigned g_mbits[(size_t)BB*SEQ*(SEQ/32)];

// ---------------- helpers ----------------------------------------------------
__device__ __forceinline__ void mma16n8k16f16(float* d, const uint32_t* a, uint32_t b0, uint32_t b1) {
    asm volatile("mma.sync.aligned.m16n8k16.row.col.f32.f16.f16.f32 "
                 "{%0,%1,%2,%3}, {%4,%5,%6,%7}, {%8,%9}, {%0,%1,%2,%3};"
                 : "+f"(d[0]), "+f"(d[1]), "+f"(d[2]), "+f"(d[3])
                 : "r"(a[0]), "r"(a[1]), "r"(a[2]), "r"(a[3]), "r"(b0), "r"(b1));
}
__device__ __forceinline__ void cpa16(void* s, const void* g) {
    uint32_t sa = (uint32_t)__cvta_generic_to_shared(s);
    asm volatile("cp.async.cg.shared.global [%0], [%1], 16;" :: "r"(sa), "l"(g) : "memory");
}
#define CPA_COMMIT() asm volatile("cp.async.commit_group;" ::: "memory")
#define CPA_WAIT(n)  asm volatile("cp.async.wait_group %0;" :: "n"(n) : "memory")
__device__ __forceinline__ uint32_t packh2(float lo, float hi) {
    __half2 t = __floats2half2_rn(lo, hi);
    return *reinterpret_cast<uint32_t*>(&t);
}

// ---------------- mask bit-pack ---------------------------------------------
__global__ __launch_bounds__(256) void pack_mask_kernel(const int* __restrict__ mask) {
    int gw = (blockIdx.x * 256 + threadIdx.x) >> 5;
    int lane = threadIdx.x & 31;
    size_t base = (size_t)gw * 1024;
    unsigned word = 0;
#pragma unroll
    for (int j = 0; j < 32; j++) {
        int v = mask[base + (size_t)j * 32 + lane];
        unsigned bits = __ballot_sync(0xffffffffu, v != 0);
        if (lane == j) word = bits;
    }
    g_mbits[(size_t)gw * 32 + lane] = word;
}

// ---------------- fp32 -> fp16 input conversion ------------------------------
__global__ __launch_bounds__(256) void conv_h_kernel(const float4* __restrict__ x,
                                                     __half2* __restrict__ y) {
    int i = blockIdx.x * 256 + threadIdx.x;   // over 1M float4
    float4 v = x[i];
    y[2 * i]     = __floats2half2_rn(v.x, v.y);
    y[2 * i + 1] = __floats2half2_rn(v.z, v.w);
}

// ---------------- W transpose+convert: Wt[n][k] = W[k][n] --------------------
__global__ void wtrans_kernel(const float* __restrict__ W, __half* __restrict__ Wt) {
    __shared__ float t[32][33];
    int bx = blockIdx.x * 32, by = blockIdx.y * 32;
    int tx = threadIdx.x, ty = threadIdx.y;   // 32 x 8
#pragma unroll
    for (int j = 0; j < 4; j++)
        t[ty + j * 8][tx] = W[(size_t)(by + ty + j * 8) * DM + bx + tx];
    __syncthreads();
#pragma unroll
    for (int j = 0; j < 4; j++)
        Wt[(size_t)(bx + ty + j * 8) * DM + by + tx] = __float2half_rn(t[tx][ty + j * 8]);
}

// ---------------- GEMM fp16 m16n8k16, cp.async double buffer -----------------
// C[8192x512] = A[8192x512] * W[512x512], A and W^T in fp16, accum fp32.
// BM=BN=128, BK=32 halves, 256 thr, 8 warps (warp tile 32x64).
__global__ __launch_bounds__(256, 2) void gemm_f16_kernel(const __half* __restrict__ Ah,
                                                          const __half* __restrict__ Wt,
                                                          int mode) {
    const __half* Asrc = (mode == 3) ? g_ctxh : Ah;
    __shared__ __half Ash[2][128][40];   // rows stride 20 words; frag bank (4g+cL)&31 perfect
    __shared__ __half Bsh[2][128][40];   // [n][k] halves

    const int tid = threadIdx.x;
    const int wid = tid >> 5, lane = tid & 31;
    const int g = lane >> 2, t = lane & 3;
    const int wm = (wid & 3) * 32;
    const int wn = (wid >> 2) * 64;
    const int m0 = blockIdx.y * 128, n0 = blockIdx.x * 128;

    // staging: 2 thr/row, each covers 2 segs of 8 halves (16B)
    const int arow = tid >> 1, asb = (tid & 1) * 2;
    const __half* ApA = Asrc + (size_t)(m0 + arow) * DM + asb * 8;
    const __half* ApB = Wt   + (size_t)(n0 + arow) * DM + asb * 8;

    float Cc[2][8][4];
#pragma unroll
    for (int i = 0; i < 2; i++)
#pragma unroll
        for (int nn = 0; nn < 8; nn++)
#pragma unroll
            for (int r = 0; r < 4; r++) Cc[i][nn][r] = 0.f;

#pragma unroll
    for (int u = 0; u < 2; u++) {
        cpa16(&Ash[0][arow][(asb + u) * 8], ApA + u * 8);
        cpa16(&Bsh[0][arow][(asb + u) * 8], ApB + u * 8);
    }
    CPA_COMMIT();

    for (int it = 0; it < DM / 32; it++) {
        const int cur = it & 1;
        if (it + 1 < DM / 32) {
            const int nxt = cur ^ 1;
            const int k0n = (it + 1) * 32;
#pragma unroll
            for (int u = 0; u < 2; u++) {
                cpa16(&Ash[nxt][arow][(asb + u) * 8], ApA + k0n + u * 8);
                cpa16(&Bsh[nxt][arow][(asb + u) * 8], ApB + k0n + u * 8);
            }
            CPA_COMMIT();
            CPA_WAIT(1);
        } else {
            CPA_WAIT(0);
        }
        __syncthreads();

        const uint32_t* Aw = (const uint32_t*)Ash[cur];
        const uint32_t* Bw = (const uint32_t*)Bsh[cur];
#pragma unroll
        for (int kk = 0; kk < 2; kk++) {
            const int kb = kk * 8;
            uint32_t a[2][4];
#pragma unroll
            for (int i = 0; i < 2; i++) {
                int rbase = (wm + i * 16 + g) * 20;
                a[i][0] = Aw[rbase + kb + t];
                a[i][1] = Aw[rbase + 160 + kb + t];      // +8 rows * 20
                a[i][2] = Aw[rbase + kb + t + 4];
                a[i][3] = Aw[rbase + 160 + kb + t + 4];
            }
#pragma unroll
            for (int nn = 0; nn < 8; nn++) {
                uint32_t b0 = Bw[(wn + nn * 8 + g) * 20 + kb + t];
                uint32_t b1 = Bw[(wn + nn * 8 + g) * 20 + kb + t + 4];
#pragma unroll
                for (int i = 0; i < 2; i++) mma16n8k16f16(Cc[i][nn], a[i], b0, b1);
            }
        }
        __syncthreads();
    }

    // epilogue: rows (wm+16i+g, +8), cols (wn+nn*8+2t, +1); h=(n0+coln)>>6
    const int hbase = n0 >> 6;
#pragma unroll
    for (int i = 0; i < 2; i++) {
#pragma unroll
        for (int rr = 0; rr < 2; rr++) {
            int m = m0 + wm + i * 16 + g + rr * 8;
            int bidx = m >> 11, s = m & 2047;
#pragma unroll
            for (int nn = 0; nn < 8; nn++) {
                int coln = wn + nn * 8 + 2 * t;
                float2 v = make_float2(Cc[i][nn][rr * 2 + 0], Cc[i][nn][rr * 2 + 1]);
                if (mode == 3) {
                    *(float2*)&g_tmp[(size_t)m * DM + n0 + coln] = v;
                } else {
                    int hh = hbase + (coln >> 6);
                    int d = coln & 63;
                    int bh = bidx * HH + hh;
                    if (mode == 2) {
                        g_Vt[((size_t)bh * DH + d)     * SEQ + s] = __float2half_rn(v.x);
                        g_Vt[((size_t)bh * DH + d + 1) * SEQ + s] = __float2half_rn(v.y);
                    } else {
                        __half2 hv = __floats2half2_rn(v.x, v.y);
                        __half* dst = (mode == 0) ? g_Qh : g_Kh;
                        *(__half2*)&dst[((size_t)bh * SEQ + s) * DH + d] = hv;
                    }
                }
            }
        }
    }
}

// ---------------- fp16 attention, two-pass (no separate norm kernel) ---------
// Pass A: QK + exp -> lsum.  Pass B: QK + exp, STG normalized attn, PV(normalized p).
#define QS_OFF 0
#define K_OFF  (128 * 72)
#define V_OFF  (K_OFF + 2 * 64 * 72)
#define TILE_H (64 * 72)
#define SMEM_ATTN ((128 * 72 + 4 * 64 * 72) * 2)
__global__ __launch_bounds__(256, 2) void attn_mma_kernel(float* __restrict__ attn_out) {
    extern __shared__ __half smh[];

    const int tid  = threadIdx.x;
    const int w    = tid >> 5;
    const int lane = tid & 31;
    const int gid  = lane >> 2;
    const int cL   = lane & 3;
    const int bh   = blockIdx.y;
    const int b    = bh >> 3, h = bh & 7;
    const int q0   = blockIdx.x * QT;
    const int lr   = w * 16 + gid;

    const __half* Qg = g_Qh + (size_t)bh * SEQ * DH;
    const __half* Kg = g_Kh + (size_t)bh * SEQ * DH;
    const __half* Vg = g_Vt + (size_t)bh * DH * SEQ;

    // ---- stage Q tile [128][64h] ----
#pragma unroll
    for (int j = 0; j < 4; j++) {
        int flat = j * 256 + tid;
        int row = flat >> 3, seg = flat & 7;
        cpa16(&smh[QS_OFF + row * 72 + seg * 8], Qg + (size_t)(q0 + row) * DH + seg * 8);
    }
    CPA_COMMIT();
    CPA_WAIT(0);
    __syncthreads();

    uint32_t qa[4][4];
    {
        const uint32_t* Q2 = (const uint32_t*)smh;
#pragma unroll
        for (int kk = 0; kk < 4; kk++) {
            qa[kk][0] = Q2[lr * 36 + kk * 8 + cL];
            qa[kk][1] = Q2[(lr + 8) * 36 + kk * 8 + cL];
            qa[kk][2] = Q2[lr * 36 + kk * 8 + cL + 4];
            qa[kk][3] = Q2[(lr + 8) * 36 + kk * 8 + cL + 4];
        }
    }

    const size_t mrow0 = ((size_t)b * SEQ + q0 + lr) * (SEQ / 32);
    const size_t mrow1 = ((size_t)b * SEQ + q0 + lr + 8) * (SEQ / 32);
    float* aprow0 = attn_out + ((size_t)bh * SEQ + q0 + lr) * SEQ;
    float* aprow1 = aprow0 + 8 * SEQ;

    const int srow = tid >> 2;
    const int sseg = (tid & 3) * 2;
    float lsum0 = 0.f, lsum1 = 0.f;

    // ================= PASS A: lsum only (K staging only) =================
#pragma unroll
    for (int u = 0; u < 2; u++)
        cpa16(&smh[K_OFF + srow * 72 + (sseg + u) * 8], Kg + (size_t)srow * DH + (sseg + u) * 8);
    CPA_COMMIT();

    for (int i = 0; i < NIT; i++) {
        const int k0 = i * KT;
        const int cur = i & 1;
        if (i + 1 < NIT) {
            const int nxt = cur ^ 1;
            const int kn = k0 + KT;
#pragma unroll
            for (int u = 0; u < 2; u++)
                cpa16(&smh[K_OFF + nxt * TILE_H + srow * 72 + (sseg + u) * 8],
                      Kg + (size_t)(kn + srow) * DH + (sseg + u) * 8);
            CPA_COMMIT();
            CPA_WAIT(1);
        } else {
            CPA_WAIT(0);
        }
        uint2 m2l = *(const uint2*)&g_mbits[mrow0 + (k0 >> 5)];
        uint2 m2h = *(const uint2*)&g_mbits[mrow1 + (k0 >> 5)];
        __syncthreads();

        const uint32_t* Kw = (const uint32_t*)(smh + K_OFF + cur * TILE_H);
        float S[8][4];
#pragma unroll
        for (int n = 0; n < 8; n++)
#pragma unroll
            for (int r = 0; r < 4; r++) S[n][r] = 0.f;
#pragma unroll
        for (int kk = 0; kk < 4; kk++) {
#pragma unroll
            for (int n = 0; n < 8; n++) {
                uint32_t b0 = Kw[(n * 8 + gid) * 36 + kk * 8 + cL];
                uint32_t b1 = Kw[(n * 8 + gid) * 36 + kk * 8 + cL + 4];
                mma16n8k16f16(S[n], qa[kk], b0, b1);
            }
        }
        unsigned ml[2] = {m2l.x, m2l.y};
        unsigned mh[2] = {m2h.x, m2h.y};
#pragma unroll
        for (int n = 0; n < 8; n++) {
            int shift = (n & 3) * 8 + 2 * cL;
            unsigned bl  = ml[n >> 2] >> shift;
            unsigned bhh = mh[n >> 2] >> shift;
            lsum0 += ((bl  & 1u) ? 0.f : __expf(S[n][0] * 0.125f))
                   + ((bl  & 2u) ? 0.f : __expf(S[n][1] * 0.125f));
            lsum1 += ((bhh & 1u) ? 0.f : __expf(S[n][2] * 0.125f))
                   + ((bhh & 2u) ? 0.f : __expf(S[n][3] * 0.125f));
        }
        __syncthreads();
    }

    // reduce lsum across the 4-lane row group
    lsum0 += __shfl_xor_sync(0xffffffffu, lsum0, 1);
    lsum0 += __shfl_xor_sync(0xffffffffu, lsum0, 2);
    lsum1 += __shfl_xor_sync(0xffffffffu, lsum1, 1);
    lsum1 += __shfl_xor_sync(0xffffffffu, lsum1, 2);
    const float inv0 = 1.0f / lsum0;
    const float inv1 = 1.0f / lsum1;

    float Cacc[8][4];
#pragma unroll
    for (int dt = 0; dt < 8; dt++)
#pragma unroll
        for (int r = 0; r < 4; r++) Cacc[dt][r] = 0.f;

    // ================= PASS B: normalized STG + PV =================
#pragma unroll
    for (int u = 0; u < 2; u++) {
        int sg = sseg + u;
        cpa16(&smh[K_OFF + srow * 72 + sg * 8], Kg + (size_t)srow * DH + sg * 8);
        cpa16(&smh[V_OFF + srow * 72 + sg * 8], Vg + (size_t)srow * SEQ + sg * 8);
    }
    CPA_COMMIT();

    for (int i = 0; i < NIT; i++) {
        const int k0 = i * KT;
        const int cur = i & 1;
        if (i + 1 < NIT) {
            const int nxt = cur ^ 1;
            const int kn = k0 + KT;
#pragma unroll
            for (int u = 0; u < 2; u++) {
                int sg = sseg + u;
                cpa16(&smh[K_OFF + nxt * TILE_H + srow * 72 + sg * 8],
                      Kg + (size_t)(kn + srow) * DH + sg * 8);
                cpa16(&smh[V_OFF + nxt * TILE_H + srow * 72 + sg * 8],
                      Vg + (size_t)srow * SEQ + kn + sg * 8);
            }
            CPA_COMMIT();
            CPA_WAIT(1);
        } else {
            CPA_WAIT(0);
        }
        uint2 m2l = *(const uint2*)&g_mbits[mrow0 + (k0 >> 5)];
        uint2 m2h = *(const uint2*)&g_mbits[mrow1 + (k0 >> 5)];
        __syncthreads();

        const uint32_t* Kw = (const uint32_t*)(smh + K_OFF + cur * TILE_H);
        const uint32_t* Vw = (const uint32_t*)(smh + V_OFF + cur * TILE_H);

        float S[8][4];
#pragma unroll
        for (int n = 0; n < 8; n++)
#pragma unroll
            for (int r = 0; r < 4; r++) S[n][r] = 0.f;
#pragma unroll
        for (int kk = 0; kk < 4; kk++) {
#pragma unroll
            for (int n = 0; n < 8; n++) {
                uint32_t b0 = Kw[(n * 8 + gid) * 36 + kk * 8 + cL];
                uint32_t b1 = Kw[(n * 8 + gid) * 36 + kk * 8 + cL + 4];
                mma16n8k16f16(S[n], qa[kk], b0, b1);
            }
        }

        unsigned ml[2] = {m2l.x, m2l.y};
        unsigned mh[2] = {m2h.x, m2h.y};
        uint32_t h01[8], h23[8];
#pragma unroll
        for (int n = 0; n < 8; n++) {
            int shift = (n & 3) * 8 + 2 * cL;
            unsigned bl  = ml[n >> 2] >> shift;
            unsigned bhh = mh[n >> 2] >> shift;
            float e0 = (bl  & 1u) ? 0.f : __expf(S[n][0] * 0.125f) * inv0;
            float e1 = (bl  & 2u) ? 0.f : __expf(S[n][1] * 0.125f) * inv0;
            float e2 = (bhh & 1u) ? 0.f : __expf(S[n][2] * 0.125f) * inv1;
            float e3 = (bhh & 2u) ? 0.f : __expf(S[n][3] * 0.125f) * inv1;
            int col = k0 + n * 8 + 2 * cL;
            *(float2*)(aprow0 + col) = make_float2(e0, e1);
            *(float2*)(aprow1 + col) = make_float2(e2, e3);
            h01[n] = packh2(e0, e1);
            h23[n] = packh2(e2, e3);
        }

#pragma unroll
        for (int s = 0; s < 4; s++) {
            uint32_t pa[4] = {h01[2 * s], h23[2 * s], h01[2 * s + 1], h23[2 * s + 1]};
#pragma unroll
            for (int dt = 0; dt < 8; dt++) {
                uint32_t b0 = Vw[(dt * 8 + gid) * 36 + s * 8 + cL];
                uint32_t b1 = Vw[(dt * 8 + gid) * 36 + s * 8 + cL + 4];
                mma16n8k16f16(Cacc[dt], pa, b0, b1);
            }
        }
        __syncthreads();
    }

    // ctx (already normalized) -> fp16
    __half* cp0 = g_ctxh + ((size_t)b * SEQ + q0 + lr) * DM + h * DH;
    __half* cp1 = cp0 + 8 * DM;
#pragma unroll
    for (int dt = 0; dt < 8; dt++) {
        int col = dt * 8 + 2 * cL;
        *(__half2*)&cp0[col] = __floats2half2_rn(Cacc[dt][0], Cacc[dt][1]);
        *(__half2*)&cp1[col] = __floats2half2_rn(Cacc[dt][2], Cacc[dt][3]);
    }
}

// ---------------- layernorm(tmp + input_Q) ----------------------------------
__global__ __launch_bounds__(256) void ln_kernel(const float* __restrict__ inQ,
                                                 const float* __restrict__ gamma,
                                                 const float* __restrict__ beta,
                                                 float* __restrict__ out) {
    int row = blockIdx.x;
    int tid = threadIdx.x;
    const float* t  = g_tmp + (size_t)row * DM;
    const float* xq = inQ  + (size_t)row * DM;
    float2 a  = *(const float2*)(t  + tid * 2);
    float2 b2 = *(const float2*)(xq + tid * 2);
    float x0 = a.x + b2.x, x1 = a.y + b2.y;
    float s  = x0 + x1;
    float sq = x0 * x0 + x1 * x1;
#pragma unroll
    for (int o = 16; o; o >>= 1) {
        s  += __shfl_xor_sync(0xffffffffu, s,  o);
        sq += __shfl_xor_sync(0xffffffffu, sq, o);
    }
    __shared__ float ws[8], wq[8];
    int w = tid >> 5, lane = tid & 31;
    if (lane == 0) { ws[w] = s; wq[w] = sq; }
    __syncthreads();
    float ts = 0.f, tq = 0.f;
#pragma unroll
    for (int k = 0; k < 8; k++) { ts += ws[k]; tq += wq[k]; }
    float mu  = ts * (1.f / DM);
    float var = tq * (1.f / DM) - mu * mu;
    float r = rsqrtf(var + 1e-5f);
    float2 g  = *(const float2*)(gamma + tid * 2);
    float2 be = *(const float2*)(beta  + tid * 2);
    float2 o;
    o.x = (x0 - mu) * r * g.x + be.x;
    o.y = (x1 - mu) * r * g.y + be.y;
    *(float2*)(out + (size_t)row * DM + tid * 2) = o;
}

// ---------------- launch ----------------------------------------------------
extern "C" void kernel_launch(void* const* d_in, const int* in_sizes, int n_in,
                              void* d_out, int out_size) {
    const float* inQ  = (const float*)d_in[0];
    const float* inK  = (const float*)d_in[1];
    const float* inV  = (const float*)d_in[2];
    const int*   mask = (const int*)d_in[3];
    const float* WQ   = (const float*)d_in[4];
    const float* WK   = (const float*)d_in[5];
    const float* WV   = (const float*)d_in[6];
    const float* Wfc  = (const float*)d_in[7];
    const float* gamma = (const float*)d_in[8];
    const float* beta  = (const float*)d_in[9];

    float* out = (float*)d_out;
    const long OUT_ELEMS = (long)BB * SEQ * DM;
    float* attn_out = out + OUT_ELEMS;

    pack_mask_kernel<<<2048, 256>>>(mask);

    // resolve device-symbol addresses (host side, graph-safe: no allocation)
    __half* inh_p;  cudaGetSymbolAddress((void**)&inh_p, g_inh);
    __half* wth_p;  cudaGetSymbolAddress((void**)&wth_p, g_Wth);

    conv_h_kernel<<<4096, 256>>>((const float4*)inQ, (__half2*)(inh_p + 0 * (size_t)BB*SEQ*DM));
    conv_h_kernel<<<4096, 256>>>((const float4*)inK, (__half2*)(inh_p + 1 * (size_t)BB*SEQ*DM));
    conv_h_kernel<<<4096, 256>>>((const float4*)inV, (__half2*)(inh_p + 2 * (size_t)BB*SEQ*DM));
    dim3 wtb(32, 8), wtg(16, 16);
    wtrans_kernel<<<wtg, wtb>>>(WQ,  wth_p + 0 * (size_t)DM*DM);
    wtrans_kernel<<<wtg, wtb>>>(WK,  wth_p + 1 * (size_t)DM*DM);
    wtrans_kernel<<<wtg, wtb>>>(WV,  wth_p + 2 * (size_t)DM*DM);
    wtrans_kernel<<<wtg, wtb>>>(Wfc, wth_p + 3 * (size_t)DM*DM);

    dim3 gb(4, 64);
    gemm_f16_kernel<<<gb, 256>>>(inh_p + 0 * (size_t)BB*SEQ*DM, wth_p + 0 * (size_t)DM*DM, 0);
    gemm_f16_kernel<<<gb, 256>>>(inh_p + 1 * (size_t)BB*SEQ*DM, wth_p + 1 * (size_t)DM*DM, 1);
    gemm_f16_kernel<<<gb, 256>>>(inh_p + 2 * (size_t)BB*SEQ*DM, wth_p + 2 * (size_t)DM*DM, 2);

    cudaFuncSetAttribute(attn_mma_kernel, cudaFuncAttributeMaxDynamicSharedMemorySize, SMEM_ATTN);
    attn_mma_kernel<<<dim3(SEQ / QT, BHN), 256, SMEM_ATTN>>>(attn_out);

    gemm_f16_kernel<<<gb, 256>>>(inh_p /*ignored for mode 3*/, wth_p + 3 * (size_t)DM*DM, 3);
    ln_kernel<<<BB * SEQ, 256>>>(inQ, gamma, beta, out);
}

// round 14
// speedup vs baseline: 1.7934x; 1.0157x over previous
#include <cuda_runtime.h>
#include <cuda_fp16.h>
#include <cstdint>

#define BB 4
#define HH 8
#define SEQ 2048
#define DM 512
#define DH 64
#define BHN (BB*HH)
#define QT 128
#define KT 64
#define NIT (SEQ/KT)

// ---------------- scratch ---------------------------------------------------
__device__ __half g_inh[3][(size_t)BB*SEQ*DM];     // inputs Q/K/V in fp16
__device__ __half g_Wth[4][DM*DM];                 // W^T in fp16: [n][k]
__device__ __half g_Qh[(size_t)BHN*SEQ*DH];        // [bh][s][d]  (d pair-permuted)
__device__ __half g_Kh[(size_t)BHN*SEQ*DH];        // [bh][s][d]  (d pair-permuted)
__device__ __half g_Vt[(size_t)BHN*DH*SEQ];        // [bh][d][s]  (s pair-permuted)
__device__ __half g_ctxh[(size_t)BB*SEQ*DM];       // fp16 ctx
__device__ float g_tmp[BB*SEQ*DM];                 // fc output (fp32) for LN
__device__ unsigned g_mbits[(size_t)BB*SEQ*(SEQ/32)];

// ---------------- helpers ----------------------------------------------------
__device__ __forceinline__ void mma16n8k16f16(float* d, const uint32_t* a, uint32_t b0, uint32_t b1) {
    asm volatile("mma.sync.aligned.m16n8k16.row.col.f32.f16.f16.f32 "
                 "{%0,%1,%2,%3}, {%4,%5,%6,%7}, {%8,%9}, {%0,%1,%2,%3};"
                 : "+f"(d[0]), "+f"(d[1]), "+f"(d[2]), "+f"(d[3])
                 : "r"(a[0]), "r"(a[1]), "r"(a[2]), "r"(a[3]), "r"(b0), "r"(b1));
}
__device__ __forceinline__ void cpa16(void* s, const void* g) {
    uint32_t sa = (uint32_t)__cvta_generic_to_shared(s);
    asm volatile("cp.async.cg.shared.global [%0], [%1], 16;" :: "r"(sa), "l"(g) : "memory");
}
#define CPA_COMMIT() asm volatile("cp.async.commit_group;" ::: "memory")
#define CPA_WAIT(n)  asm volatile("cp.async.wait_group %0;" :: "n"(n) : "memory")
__device__ __forceinline__ uint32_t packh2(float lo, float hi) {
    __half2 t = __floats2half2_rn(lo, hi);
    return *reinterpret_cast<uint32_t*>(&t);
}
// fragment-pair permutation within a 16-half group (word p of 8 -> new slot)
__device__ __forceinline__ int pairperm(int p) {   // p in 0..7
    return (p < 4) ? 2 * p : 2 * (p - 4) + 1;
}

// ---------------- mask bit-pack ---------------------------------------------
__global__ __launch_bounds__(256) void pack_mask_kernel(const int* __restrict__ mask) {
    int gw = (blockIdx.x * 256 + threadIdx.x) >> 5;
    int lane = threadIdx.x & 31;
    size_t base = (size_t)gw * 1024;
    unsigned word = 0;
#pragma unroll
    for (int j = 0; j < 32; j++) {
        int v = mask[base + (size_t)j * 32 + lane];
        unsigned bits = __ballot_sync(0xffffffffu, v != 0);
        if (lane == j) word = bits;
    }
    g_mbits[(size_t)gw * 32 + lane] = word;
}

// ---------------- fp32 -> fp16 input conversion ------------------------------
__global__ __launch_bounds__(256) void conv_h_kernel(const float4* __restrict__ x,
                                                     __half2* __restrict__ y) {
    int i = blockIdx.x * 256 + threadIdx.x;
    float4 v = x[i];
    y[2 * i]     = __floats2half2_rn(v.x, v.y);
    y[2 * i + 1] = __floats2half2_rn(v.z, v.w);
}

// ---------------- W transpose+convert: Wt[n][k] = W[k][n] --------------------
__global__ void wtrans_kernel(const float* __restrict__ W, __half* __restrict__ Wt) {
    __shared__ float t[32][33];
    int bx = blockIdx.x * 32, by = blockIdx.y * 32;
    int tx = threadIdx.x, ty = threadIdx.y;   // 32 x 8
#pragma unroll
    for (int j = 0; j < 4; j++)
        t[ty + j * 8][tx] = W[(size_t)(by + ty + j * 8) * DM + bx + tx];
    __syncthreads();
#pragma unroll
    for (int j = 0; j < 4; j++)
        Wt[(size_t)(bx + ty + j * 8) * DM + by + tx] = __float2half_rn(t[tx][ty + j * 8]);
}

// ---------------- GEMM fp16 m16n8k16, cp.async double buffer -----------------
__global__ __launch_bounds__(256, 2) void gemm_f16_kernel(const __half* __restrict__ Ah,
                                                          const __half* __restrict__ Wt,
                                                          int mode) {
    const __half* Asrc = (mode == 3) ? g_ctxh : Ah;
    __shared__ __half Ash[2][128][40];
    __shared__ __half Bsh[2][128][40];

    const int tid = threadIdx.x;
    const int wid = tid >> 5, lane = tid & 31;
    const int g = lane >> 2, t = lane & 3;
    const int wm = (wid & 3) * 32;
    const int wn = (wid >> 2) * 64;
    const int m0 = blockIdx.y * 128, n0 = blockIdx.x * 128;

    const int arow = tid >> 1, asb = (tid & 1) * 2;
    const __half* ApA = Asrc + (size_t)(m0 + arow) * DM + asb * 8;
    const __half* ApB = Wt   + (size_t)(n0 + arow) * DM + asb * 8;

    float Cc[2][8][4];
#pragma unroll
    for (int i = 0; i < 2; i++)
#pragma unroll
        for (int nn = 0; nn < 8; nn++)
#pragma unroll
            for (int r = 0; r < 4; r++) Cc[i][nn][r] = 0.f;

#pragma unroll
    for (int u = 0; u < 2; u++) {
        cpa16(&Ash[0][arow][(asb + u) * 8], ApA + u * 8);
        cpa16(&Bsh[0][arow][(asb + u) * 8], ApB + u * 8);
    }
    CPA_COMMIT();

    for (int it = 0; it < DM / 32; it++) {
        const int cur = it & 1;
        if (it + 1 < DM / 32) {
            const int nxt = cur ^ 1;
            const int k0n = (it + 1) * 32;
#pragma unroll
            for (int u = 0; u < 2; u++) {
                cpa16(&Ash[nxt][arow][(asb + u) * 8], ApA + k0n + u * 8);
                cpa16(&Bsh[nxt][arow][(asb + u) * 8], ApB + k0n + u * 8);
            }
            CPA_COMMIT();
            CPA_WAIT(1);
        } else {
            CPA_WAIT(0);
        }
        __syncthreads();

        const uint32_t* Aw = (const uint32_t*)Ash[cur];
        const uint32_t* Bw = (const uint32_t*)Bsh[cur];
#pragma unroll
        for (int kk = 0; kk < 2; kk++) {
            const int kb = kk * 8;
            uint32_t a[2][4];
#pragma unroll
            for (int i = 0; i < 2; i++) {
                int rbase = (wm + i * 16 + g) * 20;
                a[i][0] = Aw[rbase + kb + t];
                a[i][1] = Aw[rbase + 160 + kb + t];
                a[i][2] = Aw[rbase + kb + t + 4];
                a[i][3] = Aw[rbase + 160 + kb + t + 4];
            }
#pragma unroll
            for (int nn = 0; nn < 8; nn++) {
                uint32_t b0 = Bw[(wn + nn * 8 + g) * 20 + kb + t];
                uint32_t b1 = Bw[(wn + nn * 8 + g) * 20 + kb + t + 4];
#pragma unroll
                for (int i = 0; i < 2; i++) mma16n8k16f16(Cc[i][nn], a[i], b0, b1);
            }
        }
        __syncthreads();
    }

    // epilogue; modes 0/1 pair-permute d, mode 2 pair-permutes token s
    const int hbase = n0 >> 6;
#pragma unroll
    for (int i = 0; i < 2; i++) {
#pragma unroll
        for (int rr = 0; rr < 2; rr++) {
            int m = m0 + wm + i * 16 + g + rr * 8;
            int bidx = m >> 11, s = m & 2047;
#pragma unroll
            for (int nn = 0; nn < 8; nn++) {
                int coln = wn + nn * 8 + 2 * t;
                float2 v = make_float2(Cc[i][nn][rr * 2 + 0], Cc[i][nn][rr * 2 + 1]);
                if (mode == 3) {
                    *(float2*)&g_tmp[(size_t)m * DM + n0 + coln] = v;
                } else {
                    int hh = hbase + (coln >> 6);
                    int d = coln & 63;
                    int bh = bidx * HH + hh;
                    if (mode == 2) {
                        // permute token s within 16-token groups (pairs move together)
                        int sp = (s & ~15) | (pairperm((s >> 1) & 7) << 1) | (s & 1);
                        g_Vt[((size_t)bh * DH + d)     * SEQ + sp] = __float2half_rn(v.x);
                        g_Vt[((size_t)bh * DH + d + 1) * SEQ + sp] = __float2half_rn(v.y);
                    } else {
                        // permute d-pair within 16-half groups
                        int dn = (d & ~15) | (pairperm((d >> 1) & 7) << 1);
                        __half2 hv = __floats2half2_rn(v.x, v.y);
                        __half* dst = (mode == 0) ? g_Qh : g_Kh;
                        *(__half2*)&dst[((size_t)bh * SEQ + s) * DH + dn] = hv;
                    }
                }
            }
        }
    }
}

// ---------------- fp16 attention, two-pass, LDS.64 fragments -----------------
// Rows stride 80 halves (40 words, ==8 mod 32 -> bank-perfect LDS.64 phases).
// Pass A: QK + exp -> lsum.  Pass B: QK + exp, STG normalized attn, PV.
#define QROWH 80
#define K_OFF  (128 * QROWH)              // halves
#define TILE_H (64 * QROWH)
#define V_OFF  (K_OFF + 2 * TILE_H)
#define SMEM_ATTN ((128 * QROWH + 4 * 64 * QROWH) * 2)   // 61440 B
__global__ __launch_bounds__(256, 2) void attn_mma_kernel(float* __restrict__ attn_out) {
    extern __shared__ __half smh[];

    const int tid  = threadIdx.x;
    const int w    = tid >> 5;
    const int lane = tid & 31;
    const int gid  = lane >> 2;
    const int cL   = lane & 3;
    const int bh   = blockIdx.y;
    const int b    = bh >> 3, h = bh & 7;
    const int q0   = blockIdx.x * QT;
    const int lr   = w * 16 + gid;

    const __half* Qg = g_Qh + (size_t)bh * SEQ * DH;
    const __half* Kg = g_Kh + (size_t)bh * SEQ * DH;
    const __half* Vg = g_Vt + (size_t)bh * DH * SEQ;

    // ---- stage Q tile [128][64h] ----
#pragma unroll
    for (int j = 0; j < 4; j++) {
        int flat = j * 256 + tid;
        int row = flat >> 3, seg = flat & 7;
        cpa16(&smh[row * QROWH + seg * 8], Qg + (size_t)(q0 + row) * DH + seg * 8);
    }
    CPA_COMMIT();
    CPA_WAIT(0);
    __syncthreads();

    // Q A-frags via LDS.64 (pair-permuted layout: x=a0/a2 pair adjacency)
    uint32_t qa[4][4];
    {
        const uint2* Q2 = (const uint2*)smh;
#pragma unroll
        for (int kk = 0; kk < 4; kk++) {
            uint2 r0 = Q2[lr * 20 + kk * 4 + cL];
            uint2 r1 = Q2[(lr + 8) * 20 + kk * 4 + cL];
            qa[kk][0] = r0.x; qa[kk][1] = r1.x;
            qa[kk][2] = r0.y; qa[kk][3] = r1.y;
        }
    }

    const size_t mrow0 = ((size_t)b * SEQ + q0 + lr) * (SEQ / 32);
    const size_t mrow1 = ((size_t)b * SEQ + q0 + lr + 8) * (SEQ / 32);
    float* aprow0 = attn_out + ((size_t)bh * SEQ + q0 + lr) * SEQ;
    float* aprow1 = aprow0 + 8 * SEQ;

    const int srow = tid >> 2;
    const int sseg = (tid & 3) * 2;
    float lsum0 = 0.f, lsum1 = 0.f;

    // ================= PASS A: lsum only =================
#pragma unroll
    for (int u = 0; u < 2; u++)
        cpa16(&smh[K_OFF + srow * QROWH + (sseg + u) * 8], Kg + (size_t)srow * DH + (sseg + u) * 8);
    CPA_COMMIT();

    for (int i = 0; i < NIT; i++) {
        const int k0 = i * KT;
        const int cur = i & 1;
        if (i + 1 < NIT) {
            const int nxt = cur ^ 1;
            const int kn = k0 + KT;
#pragma unroll
            for (int u = 0; u < 2; u++)
                cpa16(&smh[K_OFF + nxt * TILE_H + srow * QROWH + (sseg + u) * 8],
                      Kg + (size_t)(kn + srow) * DH + (sseg + u) * 8);
            CPA_COMMIT();
            CPA_WAIT(1);
        } else {
            CPA_WAIT(0);
        }
        uint2 m2l = *(const uint2*)&g_mbits[mrow0 + (k0 >> 5)];
        uint2 m2h = *(const uint2*)&g_mbits[mrow1 + (k0 >> 5)];
        __syncthreads();

        const uint2* Kw2 = (const uint2*)(smh + K_OFF + cur * TILE_H);
        float S[8][4];
#pragma unroll
        for (int n = 0; n < 8; n++)
#pragma unroll
            for (int r = 0; r < 4; r++) S[n][r] = 0.f;
#pragma unroll
        for (int kk = 0; kk < 4; kk++) {
#pragma unroll
            for (int n = 0; n < 8; n++) {
                uint2 bb = Kw2[(n * 8 + gid) * 20 + kk * 4 + cL];
                mma16n8k16f16(S[n], qa[kk], bb.x, bb.y);
            }
        }
        unsigned ml[2] = {m2l.x, m2l.y};
        unsigned mh[2] = {m2h.x, m2h.y};
#pragma unroll
        for (int n = 0; n < 8; n++) {
            int shift = (n & 3) * 8 + 2 * cL;
            unsigned bl  = ml[n >> 2] >> shift;
            unsigned bhh = mh[n >> 2] >> shift;
            lsum0 += ((bl  & 1u) ? 0.f : __expf(S[n][0] * 0.125f))
                   + ((bl  & 2u) ? 0.f : __expf(S[n][1] * 0.125f));
            lsum1 += ((bhh & 1u) ? 0.f : __expf(S[n][2] * 0.125f))
                   + ((bhh & 2u) ? 0.f : __expf(S[n][3] * 0.125f));
        }
        __syncthreads();
    }

    lsum0 += __shfl_xor_sync(0xffffffffu, lsum0, 1);
    lsum0 += __shfl_xor_sync(0xffffffffu, lsum0, 2);
    lsum1 += __shfl_xor_sync(0xffffffffu, lsum1, 1);
    lsum1 += __shfl_xor_sync(0xffffffffu, lsum1, 2);
    const float inv0 = 1.0f / lsum0;
    const float inv1 = 1.0f / lsum1;

    float Cacc[8][4];
#pragma unroll
    for (int dt = 0; dt < 8; dt++)
#pragma unroll
        for (int r = 0; r < 4; r++) Cacc[dt][r] = 0.f;

    // ================= PASS B: normalized STG + PV =================
#pragma unroll
    for (int u = 0; u < 2; u++) {
        int sg = sseg + u;
        cpa16(&smh[K_OFF + srow * QROWH + sg * 8], Kg + (size_t)srow * DH + sg * 8);
        cpa16(&smh[V_OFF + srow * QROWH + sg * 8], Vg + (size_t)srow * SEQ + sg * 8);
    }
    CPA_COMMIT();

    for (int i = 0; i < NIT; i++) {
        const int k0 = i * KT;
        const int cur = i & 1;
        if (i + 1 < NIT) {
            const int nxt = cur ^ 1;
            const int kn = k0 + KT;
#pragma unroll
            for (int u = 0; u < 2; u++) {
                int sg = sseg + u;
                cpa16(&smh[K_OFF + nxt * TILE_H + srow * QROWH + sg * 8],
                      Kg + (size_t)(kn + srow) * DH + sg * 8);
                cpa16(&smh[V_OFF + nxt * TILE_H + srow * QROWH + sg * 8],
                      Vg + (size_t)srow * SEQ + kn + sg * 8);
            }
            CPA_COMMIT();
            CPA_WAIT(1);
        } else {
            CPA_WAIT(0);
        }
        uint2 m2l = *(const uint2*)&g_mbits[mrow0 + (k0 >> 5)];
        uint2 m2h = *(const uint2*)&g_mbits[mrow1 + (k0 >> 5)];
        __syncthreads();

        const uint2* Kw2 = (const uint2*)(smh + K_OFF + cur * TILE_H);
        const uint2* Vw2 = (const uint2*)(smh + V_OFF + cur * TILE_H);

        float S[8][4];
#pragma unroll
        for (int n = 0; n < 8; n++)
#pragma unroll
            for (int r = 0; r < 4; r++) S[n][r] = 0.f;
#pragma unroll
        for (int kk = 0; kk < 4; kk++) {
#pragma unroll
            for (int n = 0; n < 8; n++) {
                uint2 bb = Kw2[(n * 8 + gid) * 20 + kk * 4 + cL];
                mma16n8k16f16(S[n], qa[kk], bb.x, bb.y);
            }
        }

        unsigned ml[2] = {m2l.x, m2l.y};
        unsigned mh[2] = {m2h.x, m2h.y};
        uint32_t h01[8], h23[8];
#pragma unroll
        for (int n = 0; n < 8; n++) {
            int shift = (n & 3) * 8 + 2 * cL;
            unsigned bl  = ml[n >> 2] >> shift;
            unsigned bhh = mh[n >> 2] >> shift;
            float e0 = (bl  & 1u) ? 0.f : __expf(S[n][0] * 0.125f) * inv0;
            float e1 = (bl  & 2u) ? 0.f : __expf(S[n][1] * 0.125f) * inv0;
            float e2 = (bhh & 1u) ? 0.f : __expf(S[n][2] * 0.125f) * inv1;
            float e3 = (bhh & 2u) ? 0.f : __expf(S[n][3] * 0.125f) * inv1;
            int col = k0 + n * 8 + 2 * cL;
            *(float2*)(aprow0 + col) = make_float2(e0, e1);
            *(float2*)(aprow1 + col) = make_float2(e2, e3);
            h01[n] = packh2(e0, e1);
            h23[n] = packh2(e2, e3);
        }

#pragma unroll
        for (int s = 0; s < 4; s++) {
            uint32_t pa[4] = {h01[2 * s], h23[2 * s], h01[2 * s + 1], h23[2 * s + 1]};
#pragma unroll
            for (int dt = 0; dt < 8; dt++) {
                uint2 vv = Vw2[(dt * 8 + gid) * 20 + s * 4 + cL];
                mma16n8k16f16(Cacc[dt], pa, vv.x, vv.y);
            }
        }
        __syncthreads();
    }

    __half* cp0 = g_ctxh + ((size_t)b * SEQ + q0 + lr) * DM + h * DH;
    __half* cp1 = cp0 + 8 * DM;
#pragma unroll
    for (int dt = 0; dt < 8; dt++) {
        int col = dt * 8 + 2 * cL;
        *(__half2*)&cp0[col] = __floats2half2_rn(Cacc[dt][0], Cacc[dt][1]);
        *(__half2*)&cp1[col] = __floats2half2_rn(Cacc[dt][2], Cacc[dt][3]);
    }
}

// ---------------- layernorm(tmp + input_Q) ----------------------------------
__global__ __launch_bounds__(256) void ln_kernel(const float* __restrict__ inQ,
                                                 const float* __restrict__ gamma,
                                                 const float* __restrict__ beta,
                                                 float* __restrict__ out) {
    int row = blockIdx.x;
    int tid = threadIdx.x;
    const float* t  = g_tmp + (size_t)row * DM;
    const float* xq = inQ  + (size_t)row * DM;
    float2 a  = *(const float2*)(t  + tid * 2);
    float2 b2 = *(const float2*)(xq + tid * 2);
    float x0 = a.x + b2.x, x1 = a.y + b2.y;
    float s  = x0 + x1;
    float sq = x0 * x0 + x1 * x1;
#pragma unroll
    for (int o = 16; o; o >>= 1) {
        s  += __shfl_xor_sync(0xffffffffu, s,  o);
        sq += __shfl_xor_sync(0xffffffffu, sq, o);
    }
    __shared__ float ws[8], wq[8];
    int w = tid >> 5, lane = tid & 31;
    if (lane == 0) { ws[w] = s; wq[w] = sq; }
    __syncthreads();
    float ts = 0.f, tq = 0.f;
#pragma unroll
    for (int k = 0; k < 8; k++) { ts += ws[k]; tq += wq[k]; }
    float mu  = ts * (1.f / DM);
    float var = tq * (1.f / DM) - mu * mu;
    float r = rsqrtf(var + 1e-5f);
    float2 g  = *(const float2*)(gamma + tid * 2);
    float2 be = *(const float2*)(beta  + tid * 2);
    float2 o;
    o.x = (x0 - mu) * r * g.x + be.x;
    o.y = (x1 - mu) * r * g.y + be.y;
    *(float2*)(out + (size_t)row * DM + tid * 2) = o;
}

// ---------------- launch ----------------------------------------------------
extern "C" void kernel_launch(void* const* d_in, const int* in_sizes, int n_in,
                              void* d_out, int out_size) {
    const float* inQ  = (const float*)d_in[0];
    const float* inK  = (const float*)d_in[1];
    const float* inV  = (const float*)d_in[2];
    const int*   mask = (const int*)d_in[3];
    const float* WQ   = (const float*)d_in[4];
    const float* WK   = (const float*)d_in[5];
    const float* WV   = (const float*)d_in[6];
    const float* Wfc  = (const float*)d_in[7];
    const float* gamma = (const float*)d_in[8];
    const float* beta  = (const float*)d_in[9];

    float* out = (float*)d_out;
    const long OUT_ELEMS = (long)BB * SEQ * DM;
    float* attn_out = out + OUT_ELEMS;

    pack_mask_kernel<<<2048, 256>>>(mask);

    __half* inh_p;  cudaGetSymbolAddress((void**)&inh_p, g_inh);
    __half* wth_p;  cudaGetSymbolAddress((void**)&wth_p, g_Wth);

    conv_h_kernel<<<4096, 256>>>((const float4*)inQ, (__half2*)(inh_p + 0 * (size_t)BB*SEQ*DM));
    conv_h_kernel<<<4096, 256>>>((const float4*)inK, (__half2*)(inh_p + 1 * (size_t)BB*SEQ*DM));
    conv_h_kernel<<<4096, 256>>>((const float4*)inV, (__half2*)(inh_p + 2 * (size_t)BB*SEQ*DM));
    dim3 wtb(32, 8), wtg(16, 16);
    wtrans_kernel<<<wtg, wtb>>>(WQ,  wth_p + 0 * (size_t)DM*DM);
    wtrans_kernel<<<wtg, wtb>>>(WK,  wth_p + 1 * (size_t)DM*DM);
    wtrans_kernel<<<wtg, wtb>>>(WV,  wth_p + 2 * (size_t)DM*DM);
    wtrans_kernel<<<wtg, wtb>>>(Wfc, wth_p + 3 * (size_t)DM*DM);

    dim3 gb(4, 64);
    gemm_f16_kernel<<<gb, 256>>>(inh_p + 0 * (size_t)BB*SEQ*DM, wth_p + 0 * (size_t)DM*DM, 0);
    gemm_f16_kernel<<<gb, 256>>>(inh_p + 1 * (size_t)BB*SEQ*DM, wth_p + 1 * (size_t)DM*DM, 1);
    gemm_f16_kernel<<<gb, 256>>>(inh_p + 2 * (size_t)BB*SEQ*DM, wth_p + 2 * (size_t)DM*DM, 2);

    cudaFuncSetAttribute(attn_mma_kernel, cudaFuncAttributeMaxDynamicSharedMemorySize, SMEM_ATTN);
    attn_mma_kernel<<<dim3(SEQ / QT, BHN), 256, SMEM_ATTN>>>(attn_out);

    gemm_f16_kernel<<<gb, 256>>>(inh_p /*ignored for mode 3*/, wth_p + 3 * (size_t)DM*DM, 3);
    ln_kernel<<<BB * SEQ, 256>>>(inQ, gamma, beta, out);
}